// round 17
// baseline (speedup 1.0000x reference)
#include <cuda_runtime.h>
#include <cuda_bf16.h>
#include <cstdint>

#define Bn 128
#define En 1024
#define Kn 64
#define HDn 256
#define ROWSn 1792
#define NB_G 16           // clusters (batch groups of 8)
#define ND_G 8            // CTAs per cluster (32 dims each)
#define NCTA 128
#define NT 512
#define BT 8
#define DT 32

#define SHT 264           // ht row stride (bf16): 528B, conflict-free B reads
#define HTBUF (BT*SHT)    // 2112 bf16 per buffer
#define D_ST 9

__device__ int   g_ev[Bn*En];
__device__ float g_G[Kn*ROWSn];
__device__ int   g_mask_mode;

__device__ __forceinline__ float sigf(float x){
    return __fdividef(1.0f, 1.0f + __expf(-x));
}
__device__ __forceinline__ float tanhap(float x){
    float y; asm("tanh.approx.f32 %0,%1;" : "=f"(y) : "f"(x)); return y;
}
__device__ __forceinline__ uint32_t pk(float x, float y){
    __nv_bfloat162 h = __floats2bfloat162_rn(x, y);
    return *(uint32_t*)&h;
}
__device__ __forceinline__ void mmab(float* d, const uint32_t* a,
                                     uint32_t b0, uint32_t b1){
    asm volatile("mma.sync.aligned.m16n8k16.row.col.f32.bf16.bf16.f32 "
        "{%0,%1,%2,%3},{%4,%5,%6,%7},{%8,%9},{%0,%1,%2,%3};"
        : "+f"(d[0]),"+f"(d[1]),"+f"(d[2]),"+f"(d[3])
        : "r"(a[0]),"r"(a[1]),"r"(a[2]),"r"(a[3]),"r"(b0),"r"(b1));
}
__device__ __forceinline__ uint32_t smem_u32(const void* p){
    uint32_t a;
    asm("{ .reg .u64 t; cvta.to.shared.u64 t,%1; cvt.u32.u64 %0,t; }":"=r"(a):"l"(p));
    return a;
}

__global__ void k_init(const void* mask){
    if (threadIdx.x == 0){
        const float* mf = (const float*)mask;
        const int*   mi = (const int*)mask;
        bool okf=true, oki=true, anyf=false, anyi=false;
        for (int j=0;j<256;++j){
            float fv=mf[j];
            if(!(fv==0.0f||fv==1.0f)) okf=false; else if(fv==1.0f) anyf=true;
            int iv=mi[j];
            if(!(iv==0||iv==1)) oki=false; else if(iv==1) anyi=true;
        }
        g_mask_mode = (okf&&anyf)?2:((oki&&anyi)?1:0);
    }
}

__global__ void k_ev(const float* __restrict__ seq){
    int idx = blockIdx.x*blockDim.x + threadIdx.x;
    if (idx >= Bn*En) return;
    const float4* p = (const float4*)&seq[(size_t)idx*Kn];
    int kv = 0;
    #pragma unroll
    for (int j=0;j<Kn/4;++j){
        float4 v = __ldg(&p[j]);
        if(v.x>0.5f)kv=j*4; else if(v.y>0.5f)kv=j*4+1;
        else if(v.z>0.5f)kv=j*4+2; else if(v.w>0.5f)kv=j*4+3;
    }
    g_ev[idx] = kv;
}

__global__ void k_G(const float* __restrict__ U_w,
                    const float* __restrict__ U_b,
                    const float* __restrict__ V_b){
    int idx = blockIdx.x*blockDim.x + threadIdx.x;
    if (idx >= Kn*ROWSn) return;
    int kv = idx / ROWSn;
    int r  = idx - kv*ROWSn;
    g_G[idx] = U_w[r*Kn + kv] + U_b[r] + V_b[r];
}

__global__ void __launch_bounds__(NT,1) __cluster_dims__(ND_G,1,1)
ctlstm_main(const void*  __restrict__ mask_raw,
            const float* __restrict__ times,
            const float* __restrict__ V_w,
            const float* __restrict__ Lw,
            const float* __restrict__ scale,
            float*       __restrict__ out)
{
    __shared__ __align__(16) __nv_bfloat16 ht_s[2*HTBUF];   // 8448 B
    __shared__ float D_s[240*D_ST];                          // 8640 B
    __shared__ float out_s[4*BT*DT];                         // 4096 B
    __shared__ __align__(16) __nv_bfloat16 hto_s[BT*DT];     // 512 B
    __shared__ float lam_s[BT*8];
    __shared__ float m_s[2][BT];
    __shared__ __align__(8) unsigned long long mbars[2];

    const int tid = threadIdx.x;
    uint32_t rank;
    asm("mov.u32 %0, %%cluster_ctarank;" : "=r"(rank));
    const int dg  = (int)rank;
    const int bg  = blockIdx.x >> 3;        // cluster id
    const int b0  = bg * BT;
    const int d0g = dg * DT;

    const int wrp = tid >> 5, lane = tid & 31;
    const int gid = lane >> 2, tig = lane & 3;
    const int pb  = (tid >> 5) & 7, pd = tid & 31;    // pointwise (tid<256)
    const int bgl = b0 + pb;
    const int dgl = d0g + pd;
    const int mm  = g_mask_mode;

    // ---- prologue: bf16 A fragments (weights) persistent in registers -----
    // warp w (<15) owns cols [w*16, w*16+16): col c -> gate g=c>>5, dim c&31
    // (c<224); cols 224..231 -> Lw rows dg*8..+7 (lambda); 232+ -> zero pad
    uint32_t Af[64];
    {
        const int c0 = wrp*16 + gid, c1 = c0 + 8;
        const float* rp0 = nullptr; const float* rp1 = nullptr;
        if (wrp < 15){
            if (c0 < 224)      rp0 = &V_w[(size_t)((c0>>5)*256 + d0g + (c0&31))*256];
            else if (c0 < 232) rp0 = &Lw[(size_t)(dg*8 + (c0-224))*256];
            if (c1 < 224)      rp1 = &V_w[(size_t)((c1>>5)*256 + d0g + (c1&31))*256];
            else if (c1 < 232) rp1 = &Lw[(size_t)(dg*8 + (c1-224))*256];
        }
        #pragma unroll
        for (int kt=0; kt<16; ++kt){
            int k = kt*16 + tig*2;
            float a00 = rp0 ? __ldg(rp0+k)   : 0.f;
            float a01 = rp0 ? __ldg(rp0+k+1) : 0.f;
            float a02 = rp0 ? __ldg(rp0+k+8) : 0.f;
            float a03 = rp0 ? __ldg(rp0+k+9) : 0.f;
            float a10 = rp1 ? __ldg(rp1+k)   : 0.f;
            float a11 = rp1 ? __ldg(rp1+k+1) : 0.f;
            float a12 = rp1 ? __ldg(rp1+k+8) : 0.f;
            float a13 = rp1 ? __ldg(rp1+k+9) : 0.f;
            Af[kt*4+0]=pk(a00,a01); Af[kt*4+1]=pk(a10,a11);
            Af[kt*4+2]=pk(a02,a03); Af[kt*4+3]=pk(a12,a13);
        }
    }
    float sc_l = 1.0f;
    if (wrp == 14) sc_l = __ldg(&scale[dg*8 + gid]);

    for (int i = tid; i < 2*HTBUF/2; i += NT) ((uint32_t*)ht_s)[i] = 0u;
    if (tid < 16) m_s[tid>>3][tid&7] = 0.0f;
    if (tid == 0){
        uint32_t mb = smem_u32(mbars);
        asm volatile("mbarrier.init.shared.b64 [%0], %1;" :: "r"(mb),   "r"(ND_G) : "memory");
        asm volatile("mbarrier.init.shared.b64 [%0], %1;" :: "r"(mb+8), "r"(ND_G) : "memory");
    }
    __syncthreads();
    // peers' mbarriers + ht zeros must be visible before any remote arrive
    asm volatile("barrier.cluster.arrive.aligned;" ::: "memory");
    asm volatile("barrier.cluster.wait.aligned;"   ::: "memory");

    float ct = 0.0f, cb = 0.0f, htr = 0.0f;
    const size_t OFF1 = (size_t)Bn*En*Kn;
    const size_t BEH  = (size_t)Bn*En*HDn;
    const uint32_t mb_u32   = smem_u32(mbars);
    const uint32_t htos_u32 = smem_u32(hto_s);
    const uint32_t hts_u32  = smem_u32(ht_s);

    for (int i = 0; i <= En; ++i){
        // ---- prefetch per-step scalars (independent of ht) -----------------
        float bias[7]; float mval = 0.0f, dt = 0.0f;
        if (i < En && tid < 256){
            int kv = g_ev[bgl*En + i];
            #pragma unroll
            for (int g=0; g<7; ++g)
                bias[g] = __ldg(&g_G[(size_t)kv*ROWSn + g*256 + dgl]);
            int mi = bgl*En + i;
            if (mm==0)      mval = ((const unsigned char*)mask_raw)[mi] ? 1.0f:0.0f;
            else if (mm==1) mval = ((const int*)mask_raw)[mi] ? 1.0f:0.0f;
            else            mval = (((const float*)mask_raw)[mi]!=0.0f) ? 1.0f:0.0f;
            dt = __ldg(&times[bgl*(En+1)+i+1]) - __ldg(&times[bgl*(En+1)+i]);
        }

        // ---- wait for all 8 ht slices of this step (skip step 0: zeros) ----
        if (i > 0){
            uint32_t mb  = mb_u32 + (uint32_t)(i&1)*8u;
            uint32_t par = (uint32_t)(((i-1)>>1)&1);
            asm volatile("{\n\t.reg .pred P;\n\tWL_%=:\n\t"
                "mbarrier.try_wait.parity.acquire.cluster.shared::cta.b64 P,[%0],%1,0x989680;\n\t"
                "@P bra.uni WD_%=;\n\tbra.uni WL_%=;\n\tWD_%=:\n\t}"
                :: "r"(mb), "r"(par) : "memory");
        }

        // ---- GEMM: D[16 cols (this warp), 8 b] = W @ ht^T ------------------
        float dA[4] = {0,0,0,0}, dB[4] = {0,0,0,0};
        if (wrp < 15){
            const char* hrow = (const char*)ht_s + (i&1)*(HTBUF*2)
                             + gid*(SHT*2) + tig*4;
            #pragma unroll
            for (int kt=0; kt<16; ++kt){
                uint32_t b0r = *(const uint32_t*)(hrow + kt*32);
                uint32_t b1r = *(const uint32_t*)(hrow + kt*32 + 16);
                mmab((kt&1) ? dB : dA, &Af[kt*4], b0r, b1r);
            }
            #pragma unroll
            for (int j=0;j<4;++j) dA[j] += dB[j];
            int m0 = wrp*16 + gid, m1 = m0 + 8;
            D_s[m0*D_ST + 2*tig]     = dA[0];
            D_s[m0*D_ST + 2*tig + 1] = dA[1];
            D_s[m1*D_ST + 2*tig]     = dA[2];
            D_s[m1*D_ST + 2*tig + 1] = dA[3];
        }
        __syncthreads();

        // ---- lambda staging for step i-1 (cols 224..231 = warp 14) ---------
        if (i > 0 && wrp == 14){
            const float* mp = m_s[(i-1)&1];
            int bb = 2*tig;
            float x0 = __fdividef(dA[0], sc_l);
            float x1 = __fdividef(dA[1], sc_l);
            float l0 = sc_l * ((x0>20.0f)?x0:log1pf(__expf(x0)));
            float l1 = sc_l * ((x1>20.0f)?x1:log1pf(__expf(x1)));
            lam_s[bb*8 + gid]     = mp[bb]   * l0;
            lam_s[(bb+1)*8 + gid] = mp[bb+1] * l1;
        }

        // ---- pointwise recurrence (threads 0-255, one (b,d) cell) ----------
        if (i < En && tid < 256){
            float nn[7];
            #pragma unroll
            for (int g=0; g<7; ++g)
                nn[g] = D_s[(g*32+pd)*D_ST + pb] + bias[g];
            float ig=sigf(nn[0]), fg=sigf(nn[1]), ib=sigf(nn[2]), fb=sigf(nn[3]);
            float z=2.0f*sigf(nn[4]), og=sigf(nn[5]);
            float x6=nn[6];
            float delta = (x6>20.0f)?x6:log1pf(__expf(x6));
            float clow = fg*ct + ig*z;
            float cbn  = fb*cb + ib*z;
            float ctn  = cbn + (clow-cbn)*__expf(-dt*delta);
            float htn  = og * tanhap(ctn);
            if (mval != 0.0f){ ct=ctn; cb=cbn; htr=htn; }

            int cell = pb*DT + pd;
            out_s[0*256+cell] = mval*clow;
            out_s[1*256+cell] = mval*cbn;
            out_s[2*256+cell] = mval*delta;
            out_s[3*256+cell] = mval*og;
            hto_s[cell] = __float2bfloat16_rn(htr);
            if (pd == 0) m_s[i&1][pb] = mval;
        }
        __syncthreads();

        // ---- lambda store for step i-1 (8 b x 8 kappa) ---------------------
        if (i > 0 && tid < 16){
            int bb = tid >> 1, hf = tid & 1;
            float4 v = *(float4*)&lam_s[bb*8 + hf*4];
            *(float4*)&out[((size_t)(b0+bb)*En + (i-1))*Kn + dg*8 + hf*4] = v;
        }
        if (i == En) break;

        // ---- 4 main outputs: 64B-aligned float4 segments -------------------
        if (tid < 256){
            int a  = tid >> 6;
            int bb = (tid >> 3) & 7, d4 = tid & 7;
            float4 v = *(float4*)&out_s[a*256 + bb*DT + d4*4];
            float* dst = out + OFF1 + (size_t)a*BEH
                       + ((size_t)(b0+bb)*En + i)*HDn + d0g + d4*4;
            *(float4*)dst = v;
        }

        // ---- DSMEM broadcast: warp r sends our 512B slice to peer rank r ---
        if (tid < 256){
            int dest = tid >> 5, ch = tid & 31;
            int b = ch >> 2, part = ch & 3;
            uint4 v = *(const uint4*)((const char*)hto_s + b*64 + part*16);
            uint32_t laddr = hts_u32 + (uint32_t)(((i+1)&1)*(HTBUF*2)
                           + b*(SHT*2) + dg*64 + part*16);
            uint32_t raddr;
            asm volatile("mapa.shared::cluster.u32 %0, %1, %2;"
                         : "=r"(raddr) : "r"(laddr), "r"(dest));
            asm volatile("st.shared::cluster.v4.b32 [%0],{%1,%2,%3,%4};"
                         :: "r"(raddr),"r"(v.x),"r"(v.y),"r"(v.z),"r"(v.w)
                         : "memory");
        }
        __syncthreads();   // all our stores done before arrives
        if (tid < ND_G){
            uint32_t lmb = mb_u32 + (uint32_t)((i+1)&1)*8u;
            uint32_t rmb;
            asm volatile("mapa.shared::cluster.u32 %0, %1, %2;"
                         : "=r"(rmb) : "r"(lmb), "r"(tid));
            asm volatile("mbarrier.arrive.release.cluster.shared::cluster.b64 _,[%0];"
                         :: "r"(rmb) : "memory");
        }
    }

    // no CTA may exit while peers might still write to its smem
    asm volatile("barrier.cluster.arrive.aligned;" ::: "memory");
    asm volatile("barrier.cluster.wait.aligned;"   ::: "memory");
}

extern "C" void kernel_launch(void* const* d_in, const int* in_sizes, int n_in,
                              void* d_out, int out_size){
    const float* seq   = (const float*)d_in[0];
    const void*  mask  = d_in[1];
    const float* times = (const float*)d_in[2];
    const float* U_w   = (const float*)d_in[3];
    const float* U_b   = (const float*)d_in[4];
    const float* V_w   = (const float*)d_in[5];
    const float* V_b   = (const float*)d_in[6];
    const float* Lw    = (const float*)d_in[7];
    const float* scale = (const float*)d_in[8];
    float* out = (float*)d_out;

    k_init<<<1, 32>>>(mask);
    k_ev<<<(Bn*En + 127)/128, 128>>>(seq);
    k_G<<<(Kn*ROWSn + 255)/256, 256>>>(U_w, U_b, V_b);
    ctlstm_main<<<NCTA, NT>>>(mask, times, V_w, Lw, scale, out);
}